// round 14
// baseline (speedup 1.0000x reference)
#include <cuda_runtime.h>
#include <cstdint>

// Problem constants
#define SEQ_L   2048      // SEQ_LEN - 1
#define NFEAT   11
#define NBATCH  1024
#define TPB     256
#define EPT     (SEQ_L / TPB)        // 8 elements per thread

// Mask rows as 8-bit masks, bit i = mask element i.
//  0:[0,1,0,0,0,0,0,0]=0x02  1:[0,1,1,0,0,0,0,0]=0x06  2:[0,0,0,0,1,0,0,0]=0x10
//  3:[0,0,0,1,1,1,1,1]=0xF8  7:[0,0,0,0,0,0,0,1]=0x80  4,5,6,8 = 0
#define B_FULL  0xF8u
#define B_NO_TS 0x20u
#define B_NO_TP 0x40u

__device__ __forceinline__ unsigned base_bits(int v) {
    unsigned b = 0u;
    b = (v == 0) ? 0x02u : b;
    b = (v == 1) ? 0x06u : b;
    b = (v == 2) ? 0x10u : b;
    b = (v == 3) ? 0xF8u : b;
    b = (v == 7) ? 0x80u : b;
    return b;
}

__device__ __forceinline__ uint4 expand4(unsigned nib) {
    // nib: low 4 bits -> 4 floats (0.0 / 1.0)
    uint4 r;
    r.x = (nib & 1u) ? 0x3F800000u : 0u;
    r.y = (nib & 2u) ? 0x3F800000u : 0u;
    r.z = (nib & 4u) ? 0x3F800000u : 0u;
    r.w = (nib & 8u) ? 0x3F800000u : 0u;
    return r;
}

__global__ __launch_bounds__(TPB)
void mask_type_prob_kernel(const int* __restrict__ in,
                           uint4* __restrict__ out) {
    const int b   = blockIdx.x;
    const int tid = threadIdx.x;

    __shared__ int s5[TPB / 32];
    __shared__ int s6[TPB / 32];

    const int* row  = in  + (size_t)b * SEQ_L * NFEAT;
    uint4*     orow = out + (size_t)b * (SEQ_L * 2);

    // ---- Phase 1: gather (8 loads in flight), track first 5 / 6 ----
    int g[EPT];
    int f5 = SEQ_L, f6 = SEQ_L;   // sentinel "never"

#pragma unroll
    for (int k = 0; k < EPT; ++k) {
        const int t = tid + k * TPB;
        g[k] = __ldg(row + (size_t)t * NFEAT);
    }

    // ---- Phase 2: IMMEDIATE stores for static-mask elements ----
    // v outside [4,6] doesn't depend on the reduction -> store now, no barrier.
    // Thread t writes slots 2t, 2t+1 (32B contiguous); warp covers 1KB.
#pragma unroll
    for (int k = 0; k < EPT; ++k) {
        const int t = tid + k * TPB;
        const int v = g[k];
        if (v == 5) f5 = min(f5, t);
        if (v == 6) f6 = min(f6, t);
        if (v < 4 || v > 6) {
            const unsigned bits = base_bits(v);
            __stcs(orow + 2 * t,     expand4(bits));
            __stcs(orow + 2 * t + 1, expand4(bits >> 4));
        }
    }

    // ---- Phase 3: CTA reduction of first-occurrence minima ----
#pragma unroll
    for (int off = 16; off > 0; off >>= 1) {
        f5 = min(f5, __shfl_down_sync(0xFFFFFFFFu, f5, off));
        f6 = min(f6, __shfl_down_sync(0xFFFFFFFFu, f6, off));
    }
    if ((tid & 31) == 0) { s5[tid >> 5] = f5; s6[tid >> 5] = f6; }
    __syncthreads();

    int F5 = SEQ_L, F6 = SEQ_L;
#pragma unroll
    for (int i = 0; i < TPB / 32; ++i) {
        F5 = min(F5, s5[i]);
        F6 = min(F6, s6[i]);
    }

    // ---- Phase 4: stores for dynamic-mask elements (v in 4..6) ----
#pragma unroll
    for (int k = 0; k < EPT; ++k) {
        const int t = tid + k * TPB;
        const int v = g[k];
        if (v >= 4 && v <= 6) {
            // cumsum(t')==0  <=>  first occurrence > pe,  pe = min(t+1, L-1)
            const int pe = min(t + 1, SEQ_L - 1);
            const unsigned bits =
                (F5 > pe) ? B_NO_TS : ((F6 > pe) ? B_NO_TP : B_FULL);
            __stcs(orow + 2 * t,     expand4(bits));
            __stcs(orow + 2 * t + 1, expand4(bits >> 4));
        }
    }
}

extern "C" void kernel_launch(void* const* d_in, const int* in_sizes, int n_in,
                              void* d_out, int out_size) {
    const int* in = (const int*)d_in[0];
    uint4* out = (uint4*)d_out;   // float32 output: 8 floats per (b,t)
    mask_type_prob_kernel<<<NBATCH, TPB>>>(in, out);
}

// round 15
// speedup vs baseline: 1.1130x; 1.1130x over previous
#include <cuda_runtime.h>
#include <cstdint>

// Problem constants
#define SEQ_L   2048      // SEQ_LEN - 1
#define NFEAT   11
#define NBATCH  1024
#define TPB     512
#define EPT     (SEQ_L / TPB)        // 4 gt values per thread (pass 1)
#define SPT     (SEQ_L * 2 / TPB)    // 8 uint4 output slots per thread (pass 2)

// Mask rows as 8-bit masks, bit i = mask element i.
//  0:[0,1,0,0,0,0,0,0]=0x02  1:[0,1,1,0,0,0,0,0]=0x06  2:[0,0,0,0,1,0,0,0]=0x10
//  3:[0,0,0,1,1,1,1,1]=0xF8  7:[0,0,0,0,0,0,0,1]=0x80  4,5,6,8 = 0
#define B_FULL  0xF8u
#define B_NO_TS 0x20u
#define B_NO_TP 0x40u

__device__ __forceinline__ unsigned base_bits(int v) {
    unsigned b = 0u;
    b = (v == 0) ? 0x02u : b;
    b = (v == 1) ? 0x06u : b;
    b = (v == 2) ? 0x10u : b;
    b = (v == 3) ? 0xF8u : b;
    b = (v == 7) ? 0x80u : b;
    return b;
}

__device__ __forceinline__ uint4 expand4(unsigned nib) {
    // nib: low 4 bits -> 4 floats (0.0 / 1.0)
    uint4 r;
    r.x = (nib & 1u) ? 0x3F800000u : 0u;
    r.y = (nib & 2u) ? 0x3F800000u : 0u;
    r.z = (nib & 4u) ? 0x3F800000u : 0u;
    r.w = (nib & 8u) ? 0x3F800000u : 0u;
    return r;
}

__global__ __launch_bounds__(TPB)
void mask_type_prob_kernel(const int* __restrict__ in,
                           uint4* __restrict__ out) {
    const int b   = blockIdx.x;
    const int tid = threadIdx.x;

    __shared__ unsigned char sv[SEQ_L];   // gt value per t (0..8 fits a byte)
    __shared__ int s5[TPB / 32];
    __shared__ int s6[TPB / 32];

    const int* row = in + (size_t)b * SEQ_L * NFEAT;

    // L2 evict_last policy: keep input lines resident across graph replays.
    uint64_t pol;
    asm volatile("createpolicy.fractional.L2::evict_last.b64 %0, 1.0;"
                 : "=l"(pol));

    // ---- Pass 1: strided gather of gt, first occurrence of 5 / 6 ----
    int f5 = SEQ_L;   // sentinel: "never", > any prefix end
    int f6 = SEQ_L;

#pragma unroll
    for (int k = 0; k < EPT; ++k) {
        const int t = tid + k * TPB;
        int v;
        asm volatile("ld.global.L2::cache_hint.u32 %0, [%1], %2;"
                     : "=r"(v)
                     : "l"(row + (size_t)t * NFEAT), "l"(pol));
        sv[t] = (unsigned char)v;
        if (v == 5) f5 = min(f5, t);
        if (v == 6) f6 = min(f6, t);
    }

#pragma unroll
    for (int off = 16; off > 0; off >>= 1) {
        f5 = min(f5, __shfl_down_sync(0xFFFFFFFFu, f5, off));
        f6 = min(f6, __shfl_down_sync(0xFFFFFFFFu, f6, off));
    }
    const int lane = tid & 31;
    const int wid  = tid >> 5;
    if (lane == 0) { s5[wid] = f5; s6[wid] = f6; }
    __syncthreads();   // covers sv[] and s5/s6

    int F5 = SEQ_L, F6 = SEQ_L;
#pragma unroll
    for (int i = 0; i < TPB / 32; ++i) {
        F5 = min(F5, s5[i]);
        F6 = min(F6, s6[i]);
    }

    // ---- Pass 2: slot-mapped, fully coalesced evict-first stores ----
    // output row = 2048 elements * 2 uint4 = 4096 uint4 slots.
    // slot s -> element t = s>>1, half = s&1. Warp writes 512 contiguous bytes.
    uint4* orow = out + (size_t)b * (SEQ_L * 2);

#pragma unroll
    for (int k = 0; k < SPT; ++k) {
        const int slot = tid + k * TPB;
        const int t    = slot >> 1;
        const int half = slot & 1;

        const int v = (int)sv[t];
        unsigned bits;
        if (v >= 4 && v <= 6) {
            // cumsum(t')==0  <=>  first occurrence > pe,  pe = min(t+1, L-1)
            const int pe = min(t + 1, SEQ_L - 1);
            bits = (F5 > pe) ? B_NO_TS : ((F6 > pe) ? B_NO_TP : B_FULL);
        } else {
            bits = base_bits(v);
        }
        __stcs(orow + slot, expand4(bits >> (half * 4)));   // evict-first write
    }
}

extern "C" void kernel_launch(void* const* d_in, const int* in_sizes, int n_in,
                              void* d_out, int out_size) {
    const int* in = (const int*)d_in[0];
    uint4* out = (uint4*)d_out;   // float32 output: 8 floats per (b,t)
    mask_type_prob_kernel<<<NBATCH, TPB>>>(in, out);
}

// round 16
// speedup vs baseline: 1.2047x; 1.0824x over previous
#include <cuda_runtime.h>
#include <cstdint>

// Problem constants
#define SEQ_L   2048      // SEQ_LEN - 1
#define NFEAT   11
#define NBATCH  1024
#define TPB     1024
#define EPT     (SEQ_L / TPB)        // 2 gt values per thread (pass 1)
#define SPT     (SEQ_L * 2 / TPB)    // 4 uint4 output slots per thread (pass 2)

// Mask rows as 8-bit masks, bit i = mask element i.
//  0:[0,1,0,0,0,0,0,0]=0x02  1:[0,1,1,0,0,0,0,0]=0x06  2:[0,0,0,0,1,0,0,0]=0x10
//  3:[0,0,0,1,1,1,1,1]=0xF8  7:[0,0,0,0,0,0,0,1]=0x80  4,5,6,8 = 0
#define B_FULL  0xF8u
#define B_NO_TS 0x20u
#define B_NO_TP 0x40u

__device__ __forceinline__ unsigned base_bits(int v) {
    unsigned b = 0u;
    b = (v == 0) ? 0x02u : b;
    b = (v == 1) ? 0x06u : b;
    b = (v == 2) ? 0x10u : b;
    b = (v == 3) ? 0xF8u : b;
    b = (v == 7) ? 0x80u : b;
    return b;
}

__device__ __forceinline__ uint4 expand4(unsigned nib) {
    // nib: low 4 bits -> 4 floats (0.0 / 1.0)
    uint4 r;
    r.x = (nib & 1u) ? 0x3F800000u : 0u;
    r.y = (nib & 2u) ? 0x3F800000u : 0u;
    r.z = (nib & 4u) ? 0x3F800000u : 0u;
    r.w = (nib & 8u) ? 0x3F800000u : 0u;
    return r;
}

__global__ __launch_bounds__(TPB)
void mask_type_prob_kernel(const int* __restrict__ in,
                           uint4* __restrict__ out) {
    const int b   = blockIdx.x;
    const int tid = threadIdx.x;

    __shared__ unsigned char sv[SEQ_L];   // gt value per t (0..8 fits a byte)
    __shared__ int s5[TPB / 32];
    __shared__ int s6[TPB / 32];

    const int* row = in + (size_t)b * SEQ_L * NFEAT;

    // L2 evict_last policy: keep input lines resident across graph replays.
    uint64_t pol;
    asm volatile("createpolicy.fractional.L2::evict_last.b64 %0, 1.0;"
                 : "=l"(pol));

    // ---- Pass 1: strided gather of gt, first occurrence of 5 / 6 ----
    int f5 = SEQ_L;   // sentinel: "never", > any prefix end
    int f6 = SEQ_L;

#pragma unroll
    for (int k = 0; k < EPT; ++k) {
        const int t = tid + k * TPB;
        int v;
        asm volatile("ld.global.L2::cache_hint.u32 %0, [%1], %2;"
                     : "=r"(v)
                     : "l"(row + (size_t)t * NFEAT), "l"(pol));
        sv[t] = (unsigned char)v;
        if (v == 5) f5 = min(f5, t);
        if (v == 6) f6 = min(f6, t);
    }

#pragma unroll
    for (int off = 16; off > 0; off >>= 1) {
        f5 = min(f5, __shfl_down_sync(0xFFFFFFFFu, f5, off));
        f6 = min(f6, __shfl_down_sync(0xFFFFFFFFu, f6, off));
    }
    const int lane = tid & 31;
    const int wid  = tid >> 5;
    if (lane == 0) { s5[wid] = f5; s6[wid] = f6; }
    __syncthreads();   // covers sv[] and s5/s6

    int F5 = SEQ_L, F6 = SEQ_L;
#pragma unroll
    for (int i = 0; i < TPB / 32; ++i) {
        F5 = min(F5, s5[i]);
        F6 = min(F6, s6[i]);
    }

    // ---- Pass 2: slot-mapped, fully coalesced evict-first stores ----
    // output row = 2048 elements * 2 uint4 = 4096 uint4 slots.
    // slot s -> element t = s>>1, half = s&1. Warp writes 512 contiguous bytes.
    uint4* orow = out + (size_t)b * (SEQ_L * 2);

#pragma unroll
    for (int k = 0; k < SPT; ++k) {
        const int slot = tid + k * TPB;
        const int t    = slot >> 1;
        const int half = slot & 1;

        const int v = (int)sv[t];
        unsigned bits;
        if (v >= 4 && v <= 6) {
            // cumsum(t')==0  <=>  first occurrence > pe,  pe = min(t+1, L-1)
            const int pe = min(t + 1, SEQ_L - 1);
            bits = (F5 > pe) ? B_NO_TS : ((F6 > pe) ? B_NO_TP : B_FULL);
        } else {
            bits = base_bits(v);
        }
        __stcs(orow + slot, expand4(bits >> (half * 4)));   // evict-first write
    }
}

extern "C" void kernel_launch(void* const* d_in, const int* in_sizes, int n_in,
                              void* d_out, int out_size) {
    const int* in = (const int*)d_in[0];
    uint4* out = (uint4*)d_out;   // float32 output: 8 floats per (b,t)
    mask_type_prob_kernel<<<NBATCH, TPB>>>(in, out);
}